// round 4
// baseline (speedup 1.0000x reference)
#include <cuda_runtime.h>
#include <stdint.h>

// Problem constants (fixed by the dataset)
#define BATCH   2048
#define NIN     64        // n_hos * n_types
#define HIDDEN  1024
#define NSTR    512       // n_structures
#define NCOMBO  64
#define NITERS  60
#define POWITER 30

#define ROW_CAP 128       // max nnz per S row (~48 expected)
#define COL_CAP 32        // max nnz per S col (~6 expected)
#define PD_WARPS 4        // rows (warps) per PDHG CTA

// ---------------- scratch (static device globals; no allocation) ----------------
__device__ float g_tau, g_sigma;
__device__ unsigned short g_rowidx[NCOMBO * ROW_CAP];
__device__ int            g_rowcnt[NCOMBO];
__device__ unsigned short g_colidx[NSTR * COL_CAP];
__device__ int            g_colcnt[NSTR];
__device__ float g_A1[BATCH * HIDDEN];
__device__ float g_A2[BATCH * HIDDEN];
__device__ float g_Zb[BATCH * NSTR];

// ---------------- GEMM: C = relu(A[MxK] @ W[KxN] + bias) ----------------
// Templated tiles, 256 threads, register-staged double-buffered SMEM,
// float4 global loads, conflict-free padded SMEM, one __syncthreads per k-block.
template<int BM, int BN, int BK, int TM, int TN>
__global__ __launch_bounds__((BM / TM) * (BN / TN))
void gemm_bias_relu(const float* __restrict__ A, const float* __restrict__ W,
                    const float* __restrict__ bias, float* __restrict__ C,
                    int M, int N, int K)
{
    constexpr int NT  = (BM / TM) * (BN / TN);   // 256
    constexpr int BMP = BM + 4;                  // pad: (4*BMP)%32==16, BMP%4==0
    constexpr int NA4 = BM * BK / 4;             // # of A float4s per k-block
    constexpr int NB4 = BK * BN / 4;             // # of B float4s per k-block
    static_assert(NB4 == NT, "one B float4 per thread");
    static_assert(NA4 <= NT, "at most one A float4 per thread");
    static_assert(BK == 8, "indexing assumes BK==8");

    __shared__ float As[2][BK][BMP];
    __shared__ float Bs[2][BK][BN];

    const int tid  = threadIdx.x;
    const int tx   = tid % (BN / TN);
    const int ty   = tid / (BN / TN);
    const int row0 = blockIdx.y * BM;
    const int col0 = blockIdx.x * BN;

    // A load map: thread tid (< NA4) loads float4 at row ar, k-offset ac
    const int  ar = tid >> 1;
    const int  ac = (tid & 1) * 4;
    const bool a_act = (tid < NA4);
    // B load map: thread tid loads float4 at k-row br, col bc (lane-contiguous)
    const int  br = tid >> 5;
    const int  bc = (tid & 31) * 4;

    const float* Ap = A + (size_t)(row0 + ar) * K + ac;
    const float* Wp = W + (size_t)br * N + col0 + bc;

    float acc[TM][TN];
#pragma unroll
    for (int i = 0; i < TM; i++)
#pragma unroll
        for (int j = 0; j < TN; j++) acc[i][j] = 0.f;

    const int nk = K / BK;

    // prologue: fetch + store k-block 0
    float4 ra = a_act ? *(const float4*)Ap : make_float4(0.f, 0.f, 0.f, 0.f);
    float4 rb = *(const float4*)Wp;
    int buf = 0;
    if (a_act) {
        As[buf][ac + 0][ar] = ra.x; As[buf][ac + 1][ar] = ra.y;
        As[buf][ac + 2][ar] = ra.z; As[buf][ac + 3][ar] = ra.w;
    }
    *(float4*)&Bs[buf][br][bc] = rb;
    __syncthreads();

    for (int kb = 0; kb < nk; kb++) {
        if (kb + 1 < nk) {
            const int k0 = (kb + 1) * BK;
            if (a_act) ra = *(const float4*)(Ap + k0);
            rb = *(const float4*)(Wp + (size_t)k0 * N);
        }
#pragma unroll
        for (int k = 0; k < BK; k++) {
            float av[TM], bv[TN];
#pragma unroll
            for (int i = 0; i < TM; i++) av[i] = As[buf][k][ty * TM + i];
#pragma unroll
            for (int j = 0; j < TN; j++) bv[j] = Bs[buf][k][tx * TN + j];
#pragma unroll
            for (int i = 0; i < TM; i++)
#pragma unroll
                for (int j = 0; j < TN; j++)
                    acc[i][j] = fmaf(av[i], bv[j], acc[i][j]);
        }
        if (kb + 1 < nk) {
            const int nb = buf ^ 1;
            if (a_act) {
                As[nb][ac + 0][ar] = ra.x; As[nb][ac + 1][ar] = ra.y;
                As[nb][ac + 2][ar] = ra.z; As[nb][ac + 3][ar] = ra.w;
            }
            *(float4*)&Bs[nb][br][bc] = rb;
            __syncthreads();
            buf = nb;
        }
    }

    float bsv[TN];
#pragma unroll
    for (int j = 0; j < TN; j++) bsv[j] = bias[col0 + tx * TN + j];
#pragma unroll
    for (int i = 0; i < TM; i++) {
        float* Cp = C + (size_t)(row0 + ty * TM + i) * N + col0 + tx * TN;
#pragma unroll
        for (int j = 0; j < TN; j += 4) {
            float4 r;
            r.x = fmaxf(acc[i][j + 0] + bsv[j + 0], 0.f);
            r.y = fmaxf(acc[i][j + 1] + bsv[j + 1], 0.f);
            r.z = fmaxf(acc[i][j + 2] + bsv[j + 2], 0.f);
            r.w = fmaxf(acc[i][j + 3] + bsv[j + 3], 0.f);
            *(float4*)(Cp + j) = r;
        }
    }
}

// ---------------- power iteration: L = ||K||_2, tau = sigma = 0.9/L ----------------
__global__ __launch_bounds__(512) void power_kernel(const float* __restrict__ S)
{
    __shared__ float v[NSTR];
    __shared__ float sv[NCOMBO];
    __shared__ float red[16];
    __shared__ float bc;

    const int t = threadIdx.x;
    const int lane = t & 31, warp = t >> 5;

    v[t] = 1.0f / sqrtf((float)NSTR);
    __syncthreads();

    for (int it = 0; it <= POWITER; it++) {
        // sv = S @ v  (warp w handles combos 4w..4w+3)
#pragma unroll
        for (int q = 0; q < 4; q++) {
            int m = warp * 4 + q;
            float acc = 0.f;
#pragma unroll
            for (int k = 0; k < 16; k++) {
                int j = lane + 32 * k;
                acc += S[m * NSTR + j] * v[j];
            }
#pragma unroll
            for (int o = 16; o; o >>= 1) acc += __shfl_xor_sync(0xffffffffu, acc, o);
            if (lane == 0) sv[m] = acc;
        }
        __syncthreads();
        // w[t] = (S^T sv)[t] + v[t]
        float w = v[t];
#pragma unroll 8
        for (int m = 0; m < NCOMBO; m++) w += S[m * NSTR + t] * sv[m];

        float p = (it == POWITER) ? (v[t] * w) : (w * w);
#pragma unroll
        for (int o = 16; o; o >>= 1) p += __shfl_xor_sync(0xffffffffu, p, o);
        if (lane == 0) red[warp] = p;
        __syncthreads();
        if (warp == 0) {
            float s = red[lane & 15];
#pragma unroll
            for (int o = 8; o; o >>= 1) s += __shfl_xor_sync(0xffffffffu, s, o);
            if (lane == 0) bc = s;
        }
        __syncthreads();
        if (it == POWITER) {
            if (t == 0) {
                float L = sqrtf(bc);
                g_tau = 0.9f / L;
                g_sigma = 0.9f / L;
            }
        } else {
            v[t] = w / sqrtf(bc);
            __syncthreads();
        }
    }
}

// ---------------- build padded sparse index lists for S (0/1 matrix) ----------------
__global__ __launch_bounds__(512) void build_sparse(const float* __restrict__ S)
{
    const int t = threadIdx.x;
    if (t < NCOMBO) {
        int c = 0;
        for (int j = 0; j < NSTR; j++) {
            if (S[t * NSTR + j] != 0.0f) {
                if (c < ROW_CAP) g_rowidx[t * ROW_CAP + c] = (unsigned short)j;
                c++;
            }
        }
        if (c > ROW_CAP) c = ROW_CAP;
        for (int k = c; k < ROW_CAP; k++) g_rowidx[t * ROW_CAP + k] = (unsigned short)NSTR;  // dummy -> xbar[512]=0
        g_rowcnt[t] = c;
    }
    {
        int c = 0;
        for (int m = 0; m < NCOMBO; m++) {
            if (S[m * NSTR + t] != 0.0f) {
                if (c < COL_CAP) g_colidx[t * COL_CAP + c] = (unsigned short)m;
                c++;
            }
        }
        if (c > COL_CAP) c = COL_CAP;
        for (int k = c; k < COL_CAP; k++) g_colidx[t * COL_CAP + k] = (unsigned short)NCOMBO;  // dummy -> y1[64]=0
        g_colcnt[t] = c;
    }
}

// ---------------- PDHG: one warp per batch row, 60 fused iterations ----------------
__global__ __launch_bounds__(PD_WARPS * 32) void pdhg_kernel(
    const float* __restrict__ Xc,   // capacities B = X reshaped [BATCH, 64]
    const float* __restrict__ Zg,   // Z from MLP [BATCH, 512]
    float* __restrict__ out)
{
    __shared__ float xbars[PD_WARPS][516];   // 512 + dummy zero slot @512
    __shared__ float y1s[PD_WARPS][68];      // 64 + dummy zero slot @64

    const float tau = g_tau, sigma = g_sigma;
    const int warp = threadIdx.x >> 5, lane = threadIdx.x & 31;
    const int row = blockIdx.x * PD_WARPS + warp;
    float* xbar = xbars[warp];
    float* y1w  = y1s[warp];

    float Zr[16], xr[16], y2[16];
    int   ccn[16];
#pragma unroll
    for (int t = 0; t < 16; t++) {
        int j = lane + 32 * t;
        Zr[t] = Zg[(size_t)row * NSTR + j];
        xr[t] = 0.f;
        y2[t] = 0.f;
        xbar[j] = 0.f;
        ccn[t] = (g_colcnt[j] + 1) >> 1;   // pairs of u16 per uint load
    }
    if (lane == 0) { xbar[NSTR] = 0.f; y1w[NCOMBO] = 0.f; }
    const float Bc0 = Xc[(size_t)row * NCOMBO + lane];
    const float Bc1 = Xc[(size_t)row * NCOMBO + lane + 32];
    float y1a = 0.f, y1b = 0.f;
    const int n0 = (g_rowcnt[lane] + 3) >> 2;        // quads of u16 per uint2 load
    const int n1 = (g_rowcnt[lane + 32] + 3) >> 2;
    const uint2* ri0 = (const uint2*)(g_rowidx + lane * ROW_CAP);
    const uint2* ri1 = (const uint2*)(g_rowidx + (lane + 32) * ROW_CAP);
    __syncwarp();

    for (int it = 0; it < NITERS; it++) {
        // ---- y1 = max(y1 + sigma*(S@xbar - B), 0) : sparse gather of xbar ----
        float kx0 = 0.f, kx1 = 0.f;
        for (int k = 0; k < n0; k++) {
            uint2 u = ri0[k];
            kx0 += xbar[u.x & 0xffff] + xbar[u.x >> 16]
                 + xbar[u.y & 0xffff] + xbar[u.y >> 16];
        }
        for (int k = 0; k < n1; k++) {
            uint2 u = ri1[k];
            kx1 += xbar[u.x & 0xffff] + xbar[u.x >> 16]
                 + xbar[u.y & 0xffff] + xbar[u.y >> 16];
        }
        y1a = fmaxf(fmaf(sigma, kx0 - Bc0, y1a), 0.f);
        y1b = fmaxf(fmaf(sigma, kx1 - Bc1, y1b), 0.f);
        y1w[lane] = y1a;
        y1w[lane + 32] = y1b;
        __syncwarp();

        // ---- y2 update, KTy, prox_f prep ----
        float nrm2 = 0.f;
        float dv[16];
#pragma unroll
        for (int t = 0; t < 16; t++) {
            int j = lane + 32 * t;
            float xb = xbar[j];
            float y2n = fmaxf(y2[t] - sigma * xb, 0.f);
            y2[t] = y2n;
            float kty = -y2n;
            const unsigned int* pc = (const unsigned int*)(g_colidx + j * COL_CAP);
            int nc = ccn[t];
            for (int k = 0; k < nc; k++) {
                unsigned int u = pc[k];
                kty += y1w[u & 0xffff] + y1w[u >> 16];
            }
            float v = xr[t] - tau * kty;
            float d = v + tau - Zr[t];       // u = v + tau*W (W=1); d = u - Z
            dv[t] = d;
            nrm2 += d * d;
        }
#pragma unroll
        for (int o = 16; o; o >>= 1) nrm2 += __shfl_xor_sync(0xffffffffu, nrm2, o);
        float nrm = sqrtf(nrm2);
        float scale = fmaxf(1.f - tau / fmaxf(nrm, 1e-12f), 0.f);

        // ---- x_new = Z + scale*d; xbar = 2 x_new - x ----
#pragma unroll
        for (int t = 0; t < 16; t++) {
            int j = lane + 32 * t;
            float xn = fmaf(scale, dv[t], Zr[t]);
            xbar[j] = 2.f * xn - xr[t];
            xr[t] = xn;
        }
        __syncwarp();
    }

#pragma unroll
    for (int t = 0; t < 16; t++)
        out[(size_t)row * NSTR + lane + 32 * t] = xr[t];
}

// ---------------- launch ----------------
extern "C" void kernel_launch(void* const* d_in, const int* in_sizes, int n_in,
                              void* d_out, int out_size)
{
    const float* X  = (const float*)d_in[0];   // [2048,4,16] = [2048,64]
    const float* W1 = (const float*)d_in[1];   // [64,1024]
    const float* b1 = (const float*)d_in[2];
    const float* W2 = (const float*)d_in[3];   // [1024,1024]
    const float* b2 = (const float*)d_in[4];
    const float* W3 = (const float*)d_in[5];   // [1024,512]
    const float* b3 = (const float*)d_in[6];
    const float* S  = (const float*)d_in[7];   // [64,512]
    float* out = (float*)d_out;                // [2048,512]

    float *A1, *A2, *Zb;
    cudaGetSymbolAddress((void**)&A1, g_A1);
    cudaGetSymbolAddress((void**)&A2, g_A2);
    cudaGetSymbolAddress((void**)&Zb, g_Zb);

    // MLP forward (relu after every layer, matching reference)
    gemm_bias_relu<128, 128, 8, 8, 8><<<dim3(HIDDEN / 128, BATCH / 128), 256>>>(X,  W1, b1, A1, BATCH, HIDDEN, NIN);
    gemm_bias_relu<128, 128, 8, 8, 8><<<dim3(HIDDEN / 128, BATCH / 128), 256>>>(A1, W2, b2, A2, BATCH, HIDDEN, HIDDEN);
    gemm_bias_relu< 64, 128, 8, 4, 8><<<dim3(NSTR / 128,   BATCH / 64),  256>>>(A2, W3, b3, Zb, BATCH, NSTR,   HIDDEN);

    // step sizes + sparse structure of S
    power_kernel<<<1, 512>>>(S);
    build_sparse<<<1, 512>>>(S);

    // fused 60-iteration PDHG, one warp per batch row
    pdhg_kernel<<<BATCH / PD_WARPS, PD_WARPS * 32>>>(X, Zb, out);
}

// round 6
// speedup vs baseline: 2.3489x; 2.3489x over previous
#include <cuda_runtime.h>
#include <stdint.h>

// Problem constants (fixed by the dataset)
#define BATCH   2048
#define NIN     64        // n_hos * n_types
#define HIDDEN  1024
#define NSTR    512       // n_structures
#define NCOMBO  64
#define NITERS  60
#define POWITER 30

#define RPAIRS  48                 // u32 words (2 x u16 idx) per combo row
#define RCAP    (2 * RPAIRS)       // 96 u16 entries, ~48 expected (8 sigma pad)
#define CWORDS  6                  // u32 words (4 x u8 idx) per structure col
#define CCAP    (4 * CWORDS)       // 24 u8 entries, ~6 expected
#define PD_WARPS 4                 // rows (warps) per PDHG CTA

// ---------------- scratch (static device globals; no allocation) ----------------
__device__ float g_tau, g_sigma;
__device__ unsigned int g_rowPairT[RPAIRS * NCOMBO];  // [p][m]: coalesced across m
__device__ unsigned int g_colPackT[CWORDS * NSTR];    // [w][j]: coalesced across j
__device__ int          g_rowPairCntMax;              // uniform phase-1 trip count
__device__ int          g_colWordMax;                 // uniform phase-2 trip count
__device__ float g_A1[BATCH * HIDDEN];
__device__ float g_A2[BATCH * HIDDEN];
__device__ float g_Zb[BATCH * NSTR];

// ---------------- GEMM: C = relu(A[MxK] @ W[KxN] + bias) ----------------
template<int BM, int BN, int BK, int TM, int TN>
__global__ __launch_bounds__((BM / TM) * (BN / TN))
void gemm_bias_relu(const float* __restrict__ A, const float* __restrict__ W,
                    const float* __restrict__ bias, float* __restrict__ C,
                    int M, int N, int K)
{
    constexpr int NT  = (BM / TM) * (BN / TN);   // 256
    constexpr int BMP = BM + 4;                  // pad: (4*BMP)%32==16, BMP%4==0
    constexpr int NA4 = BM * BK / 4;
    constexpr int NB4 = BK * BN / 4;
    static_assert(NB4 == NT, "one B float4 per thread");
    static_assert(NA4 <= NT, "at most one A float4 per thread");
    static_assert(BK == 8, "indexing assumes BK==8");

    __shared__ float As[2][BK][BMP];
    __shared__ float Bs[2][BK][BN];

    const int tid  = threadIdx.x;
    const int tx   = tid % (BN / TN);
    const int ty   = tid / (BN / TN);
    const int row0 = blockIdx.y * BM;
    const int col0 = blockIdx.x * BN;

    const int  ar = tid >> 1;
    const int  ac = (tid & 1) * 4;
    const bool a_act = (tid < NA4);
    const int  br = tid >> 5;
    const int  bc = (tid & 31) * 4;

    const float* Ap = A + (size_t)(row0 + ar) * K + ac;
    const float* Wp = W + (size_t)br * N + col0 + bc;

    float acc[TM][TN];
#pragma unroll
    for (int i = 0; i < TM; i++)
#pragma unroll
        for (int j = 0; j < TN; j++) acc[i][j] = 0.f;

    const int nk = K / BK;

    float4 ra = a_act ? *(const float4*)Ap : make_float4(0.f, 0.f, 0.f, 0.f);
    float4 rb = *(const float4*)Wp;
    int buf = 0;
    if (a_act) {
        As[buf][ac + 0][ar] = ra.x; As[buf][ac + 1][ar] = ra.y;
        As[buf][ac + 2][ar] = ra.z; As[buf][ac + 3][ar] = ra.w;
    }
    *(float4*)&Bs[buf][br][bc] = rb;
    __syncthreads();

    for (int kb = 0; kb < nk; kb++) {
        if (kb + 1 < nk) {
            const int k0 = (kb + 1) * BK;
            if (a_act) ra = *(const float4*)(Ap + k0);
            rb = *(const float4*)(Wp + (size_t)k0 * N);
        }
#pragma unroll
        for (int k = 0; k < BK; k++) {
            float av[TM], bv[TN];
#pragma unroll
            for (int i = 0; i < TM; i++) av[i] = As[buf][k][ty * TM + i];
#pragma unroll
            for (int j = 0; j < TN; j++) bv[j] = Bs[buf][k][tx * TN + j];
#pragma unroll
            for (int i = 0; i < TM; i++)
#pragma unroll
                for (int j = 0; j < TN; j++)
                    acc[i][j] = fmaf(av[i], bv[j], acc[i][j]);
        }
        if (kb + 1 < nk) {
            const int nb = buf ^ 1;
            if (a_act) {
                As[nb][ac + 0][ar] = ra.x; As[nb][ac + 1][ar] = ra.y;
                As[nb][ac + 2][ar] = ra.z; As[nb][ac + 3][ar] = ra.w;
            }
            *(float4*)&Bs[nb][br][bc] = rb;
            __syncthreads();
            buf = nb;
        }
    }

    float bsv[TN];
#pragma unroll
    for (int j = 0; j < TN; j++) bsv[j] = bias[col0 + tx * TN + j];
#pragma unroll
    for (int i = 0; i < TM; i++) {
        float* Cp = C + (size_t)(row0 + ty * TM + i) * N + col0 + tx * TN;
#pragma unroll
        for (int j = 0; j < TN; j += 4) {
            float4 r;
            r.x = fmaxf(acc[i][j + 0] + bsv[j + 0], 0.f);
            r.y = fmaxf(acc[i][j + 1] + bsv[j + 1], 0.f);
            r.z = fmaxf(acc[i][j + 2] + bsv[j + 2], 0.f);
            r.w = fmaxf(acc[i][j + 3] + bsv[j + 3], 0.f);
            *(float4*)(Cp + j) = r;
        }
    }
}

// ---------------- prep: sparse lists (ballot-parallel) + sparse power iteration ----------------
__global__ __launch_bounds__(512) void prep_kernel(const float* __restrict__ S)
{
    __shared__ unsigned short rl[NCOMBO][RCAP];     // 12 KB
    __shared__ unsigned char  cl[NSTR][CCAP];       // 12 KB
    __shared__ unsigned int   masks[NCOMBO][16];    // 4 KB
    __shared__ int            pr[NCOMBO][16];       // 4 KB
    __shared__ int            rcnt[NCOMBO];
    __shared__ int            ccol[NSTR];
    __shared__ float v[NSTR];
    __shared__ float sv[NCOMBO];
    __shared__ float red[16];
    __shared__ float bc;
    __shared__ int   rmax, cmax;

    const int t = threadIdx.x, lane = t & 31, warp = t >> 5;

    if (t == 0) { rmax = 0; cmax = 0; }

    // pass A: per-thread column list + per-row nnz bitmasks via ballot
    int cc = 0;
    for (int m = 0; m < NCOMBO; m++) {
        float val = S[m * NSTR + t];                    // coalesced
        unsigned mask = __ballot_sync(0xffffffffu, val != 0.0f);
        if (lane == 0) masks[m][warp] = mask;
        if (val != 0.0f && cc < CCAP) cl[t][cc++] = (unsigned char)m;
    }
    ccol[t] = cc;
    for (int k = cc; k < CCAP; k++) cl[t][k] = (unsigned char)NCOMBO;  // dummy -> y1[64]=0
    for (int w = 0; w < CWORDS; w++) {
        unsigned u = (unsigned)cl[t][4*w] | ((unsigned)cl[t][4*w+1] << 8)
                   | ((unsigned)cl[t][4*w+2] << 16) | ((unsigned)cl[t][4*w+3] << 24);
        g_colPackT[w * NSTR + t] = u;
    }
    atomicMax(&cmax, (cc + 3) >> 2);
    __syncthreads();

    // prefix over 16 warp-masks per row
    if (t < NCOMBO) {
        int run = 0;
        for (int w = 0; w < 16; w++) { pr[t][w] = run; run += __popc(masks[t][w]); }
        rcnt[t] = run;
    }
    __syncthreads();

    // pass B: scatter row entries (ordered by column)
    for (int m = 0; m < NCOMBO; m++) {
        unsigned mask = masks[m][warp];
        if (mask & (1u << lane)) {
            int pos = pr[m][warp] + __popc(mask & ((1u << lane) - 1u));
            if (pos < RCAP) rl[m][pos] = (unsigned short)t;
        }
    }
    __syncthreads();
    if (t < NCOMBO) {
        int c = rcnt[t]; if (c > RCAP) c = RCAP;
        rcnt[t] = c;
        for (int k = c; k < RCAP; k++) rl[t][k] = (unsigned short)NSTR;  // dummy -> xbar[512]=0
        atomicMax(&rmax, (c + 1) >> 1);
    }
    __syncthreads();
    if (t == 0) { g_rowPairCntMax = rmax; g_colWordMax = cmax; }
    // pack transposed pairs: word idx = p*64 + m
    for (int idx = t; idx < RPAIRS * NCOMBO; idx += 512) {
        int p = idx >> 6, m = idx & 63;
        g_rowPairT[idx] = (unsigned)rl[m][2*p] | ((unsigned)rl[m][2*p+1] << 16);
    }

    // sparse power iteration: L = ||K||, tau = sigma = 0.9/L
    v[t] = 1.0f / sqrtf((float)NSTR);
    __syncthreads();
    const int m8 = t >> 3, s8 = t & 7;   // 8 threads per combo row
    for (int it = 0; it <= POWITER; it++) {
        float acc = 0.f;
        const int cnt = rcnt[m8];
        for (int k = s8; k < cnt; k += 8) acc += v[rl[m8][k]];
        acc += __shfl_down_sync(0xffffffffu, acc, 4, 8);
        acc += __shfl_down_sync(0xffffffffu, acc, 2, 8);
        acc += __shfl_down_sync(0xffffffffu, acc, 1, 8);
        if (s8 == 0) sv[m8] = acc;
        __syncthreads();

        float w = v[t];
        const int cc2 = ccol[t];
        for (int k = 0; k < cc2; k++) w += sv[cl[t][k]];

        float p = (it == POWITER) ? (v[t] * w) : (w * w);
#pragma unroll
        for (int o = 16; o; o >>= 1) p += __shfl_xor_sync(0xffffffffu, p, o);
        if (lane == 0) red[warp] = p;
        __syncthreads();
        if (warp == 0) {
            float s = red[lane & 15];
#pragma unroll
            for (int o = 8; o; o >>= 1) s += __shfl_xor_sync(0xffffffffu, s, o);
            if (lane == 0) bc = s;
        }
        __syncthreads();
        if (it == POWITER) {
            if (t == 0) {
                float L = sqrtf(bc);
                g_tau = 0.9f / L;
                g_sigma = 0.9f / L;
            }
        } else {
            v[t] = w / sqrtf(bc);
            __syncthreads();
        }
    }
}

// ---------------- PDHG: one warp per batch row, 60 fused iterations ----------------
__global__ __launch_bounds__(PD_WARPS * 32) void pdhg_kernel(
    const float* __restrict__ Xc,   // capacities B = X reshaped [BATCH, 64]
    const float* __restrict__ Zg,   // Z from MLP [BATCH, 512]
    float* __restrict__ out)
{
    __shared__ float xbars[PD_WARPS][516];   // 512 + dummy zero slot @512
    __shared__ float y1s[PD_WARPS][68];      // 64 + dummy zero slot @64

    const float tau = g_tau, sigma = g_sigma;
    const int warp = threadIdx.x >> 5, lane = threadIdx.x & 31;
    const int row = blockIdx.x * PD_WARPS + warp;
    float* xbar = xbars[warp];
    float* y1w  = y1s[warp];

    float Zr[16], xr[16], y2[16];
#pragma unroll
    for (int t = 0; t < 16; t++) {
        int j = lane + 32 * t;
        Zr[t] = Zg[(size_t)row * NSTR + j];
        xr[t] = 0.f;
        y2[t] = 0.f;
        xbar[j] = 0.f;
    }
    if (lane == 0) { xbar[NSTR] = 0.f; y1w[NCOMBO] = 0.f; }
    const float Bc0 = Xc[(size_t)row * NCOMBO + lane];
    const float Bc1 = Xc[(size_t)row * NCOMBO + lane + 32];
    float y1a = 0.f, y1b = 0.f;
    const int npair = g_rowPairCntMax;   // warp-uniform (dummies gather zeros)
    const int nword = g_colWordMax;      // warp-uniform
    __syncwarp();

    for (int it = 0; it < NITERS; it++) {
        // ---- y1 = max(y1 + sigma*(S@xbar - B), 0): coalesced transposed index loads ----
        float kx0 = 0.f, kx1 = 0.f;
#pragma unroll 4
        for (int p = 0; p < npair; p++) {
            unsigned u0 = g_rowPairT[p * 64 + lane];
            unsigned u1 = g_rowPairT[p * 64 + 32 + lane];
            kx0 += xbar[u0 & 0xffffu] + xbar[u0 >> 16];
            kx1 += xbar[u1 & 0xffffu] + xbar[u1 >> 16];
        }
        y1a = fmaxf(fmaf(sigma, kx0 - Bc0, y1a), 0.f);
        y1b = fmaxf(fmaf(sigma, kx1 - Bc1, y1b), 0.f);
        y1w[lane] = y1a;
        y1w[lane + 32] = y1b;
        __syncwarp();

        // ---- y2 update, KTy, prox_f prep ----
        float nrm2 = 0.f;
        float dv[16];
#pragma unroll
        for (int t = 0; t < 16; t++) {
            int j = lane + 32 * t;
            float xb = xbar[j];
            float y2n = fmaxf(y2[t] - sigma * xb, 0.f);
            y2[t] = y2n;
            float kty = -y2n;
            for (int w = 0; w < nword; w++) {
                unsigned u = g_colPackT[w * NSTR + j];     // coalesced across lanes
                kty += y1w[u & 255u] + y1w[(u >> 8) & 255u]
                     + y1w[(u >> 16) & 255u] + y1w[u >> 24];
            }
            float vv = xr[t] - tau * kty;
            float d = vv + tau - Zr[t];      // u = v + tau*W (W=1); d = u - Z
            dv[t] = d;
            nrm2 += d * d;
        }
#pragma unroll
        for (int o = 16; o; o >>= 1) nrm2 += __shfl_xor_sync(0xffffffffu, nrm2, o);
        float nrm = sqrtf(nrm2);
        float scale = fmaxf(1.f - tau / fmaxf(nrm, 1e-12f), 0.f);

        // ---- x_new = Z + scale*d; xbar = 2 x_new - x ----
#pragma unroll
        for (int t = 0; t < 16; t++) {
            int j = lane + 32 * t;
            float xn = fmaf(scale, dv[t], Zr[t]);
            xbar[j] = 2.f * xn - xr[t];
            xr[t] = xn;
        }
        __syncwarp();
    }

#pragma unroll
    for (int t = 0; t < 16; t++)
        out[(size_t)row * NSTR + lane + 32 * t] = xr[t];
}

// ---------------- launch ----------------
extern "C" void kernel_launch(void* const* d_in, const int* in_sizes, int n_in,
                              void* d_out, int out_size)
{
    const float* X  = (const float*)d_in[0];   // [2048,4,16] = [2048,64]
    const float* W1 = (const float*)d_in[1];   // [64,1024]
    const float* b1 = (const float*)d_in[2];
    const float* W2 = (const float*)d_in[3];   // [1024,1024]
    const float* b2 = (const float*)d_in[4];
    const float* W3 = (const float*)d_in[5];   // [1024,512]
    const float* b3 = (const float*)d_in[6];
    const float* S  = (const float*)d_in[7];   // [64,512]
    float* out = (float*)d_out;                // [2048,512]

    float *A1, *A2, *Zb;
    cudaGetSymbolAddress((void**)&A1, g_A1);
    cudaGetSymbolAddress((void**)&A2, g_A2);
    cudaGetSymbolAddress((void**)&Zb, g_Zb);

    // sparse structure + step sizes (independent of MLP)
    prep_kernel<<<1, 512>>>(S);

    // MLP forward (relu after every layer, matching reference)
    gemm_bias_relu<128, 128, 8, 8, 8><<<dim3(HIDDEN / 128, BATCH / 128), 256>>>(X,  W1, b1, A1, BATCH, HIDDEN, NIN);
    gemm_bias_relu<128, 128, 8, 8, 8><<<dim3(HIDDEN / 128, BATCH / 128), 256>>>(A1, W2, b2, A2, BATCH, HIDDEN, HIDDEN);
    gemm_bias_relu< 64, 128, 8, 4, 8><<<dim3(NSTR / 128,   BATCH / 64),  256>>>(A2, W3, b3, Zb, BATCH, NSTR,   HIDDEN);

    // fused 60-iteration PDHG, one warp per batch row
    pdhg_kernel<<<BATCH / PD_WARPS, PD_WARPS * 32>>>(X, Zb, out);
}